// round 14
// baseline (speedup 1.0000x reference)
#include <cuda_runtime.h>
#include <cuda_fp16.h>
#include <math.h>
#include <cstdint>

// ---------------- problem constants ----------------
#define EMB   1024
#define NHEAD 8
#define HDIM  64
#define NH2   16
#define DV    128
#define FFD   4096
#define BATCH 2
#define SEQ   2048
#define ROWS  (BATCH*SEQ)
#define LAM_INIT 0.35550906759096926f

// ---------------- device scratch ----------------
__device__ __half g_h [ROWS*EMB];
__device__ __half g_qh[(size_t)ROWS*EMB];
__device__ __half g_kh[(size_t)ROWS*EMB];
__device__ __half g_vh[(size_t)ROWS*EMB];
__device__ __half g_vt[(size_t)ROWS*EMB];
__device__ __half g_ao[(size_t)ROWS*EMB];
__device__ __half g_t [(size_t)ROWS*FFD];
__device__ __half g_w [(size_t)12*1024*1024];  // weight arena: QKV@0, Wo@3M, W1@4M, W2@8M
__device__ float  g_x1[ROWS*EMB];
__device__ float  g_lam;

struct QKVPtrs { __half* q; __half* k; __half* v; };

// ================= baseline-PTX helpers =================
__device__ __forceinline__ uint32_t smem_u32(const void* p) {
    uint32_t a;
    asm("{ .reg .u64 t; cvta.to.shared.u64 t, %1; cvt.u32.u64 %0, t; }" : "=r"(a) : "l"(p));
    return a;
}

__device__ __forceinline__ void cp_async16(uint32_t dst, const void* src) {
    asm volatile("cp.async.cg.shared.global [%0], [%1], 16;" :: "r"(dst), "l"(src));
}
#define CP_COMMIT() asm volatile("cp.async.commit_group;" ::: "memory")
#define CP_WAIT(n)  asm volatile("cp.async.wait_group %0;" :: "n"(n) : "memory")

__device__ __forceinline__ void ldsm4(uint32_t* r, uint32_t addr) {
    asm volatile("ldmatrix.sync.aligned.m8n8.x4.shared.b16 {%0,%1,%2,%3}, [%4];"
        : "=r"(r[0]), "=r"(r[1]), "=r"(r[2]), "=r"(r[3]) : "r"(addr));
}

__device__ __forceinline__ void mma16816h(float* d, const uint32_t* a, const uint32_t* b) {
    asm volatile("mma.sync.aligned.m16n8k16.row.col.f32.f16.f16.f32 "
        "{%0,%1,%2,%3}, {%4,%5,%6,%7}, {%8,%9}, {%0,%1,%2,%3};"
        : "+f"(d[0]), "+f"(d[1]), "+f"(d[2]), "+f"(d[3])
        : "r"(a[0]), "r"(a[1]), "r"(a[2]), "r"(a[3]), "r"(b[0]), "r"(b[1]));
}

// ================= conversion kernels (vectorized, 64x64 tiles) =================
__global__ void convert_tr3(const float* __restrict__ w0, const float* __restrict__ w1,
                            const float* __restrict__ w2, __half* __restrict__ out) {
    __shared__ float tile[64][65];
    const float* in = blockIdx.z == 0 ? w0 : (blockIdx.z == 1 ? w1 : w2);
    __half* op = out + (size_t)blockIdx.z * EMB * EMB;
    int n0 = blockIdx.x * 64, k0 = blockIdx.y * 64;
    int t = threadIdx.x;
#pragma unroll
    for (int i = 0; i < 4; i++) {
        int idx = t + i*256;
        int r = idx >> 4, c4 = (idx & 15) * 4;
        float4 v = *reinterpret_cast<const float4*>(&in[(size_t)(k0 + r)*EMB + n0 + c4]);
        tile[r][c4] = v.x; tile[r][c4+1] = v.y; tile[r][c4+2] = v.z; tile[r][c4+3] = v.w;
    }
    __syncthreads();
#pragma unroll
    for (int i = 0; i < 2; i++) {
        int idx = t + i*256;
        int r = idx >> 3, kc = (idx & 7) * 8;
        __half hs[8];
#pragma unroll
        for (int j = 0; j < 8; j++) hs[j] = __float2half(tile[kc + j][r]);
        *reinterpret_cast<uint4*>(&op[(size_t)(n0 + r)*EMB + k0 + kc]) = *reinterpret_cast<uint4*>(hs);
    }
}

__global__ void convert_w_all(const float* __restrict__ Wo, const float* __restrict__ W1,
                              const float* __restrict__ W2, __half* __restrict__ out) {
    __shared__ float tile[64][65];
    int bid = blockIdx.x;
    const float* in; __half* op; int K, N, bx, by;
    if (bid < 256)       { in = Wo; op = out + (size_t)3*1024*1024; K = EMB; N = EMB; bx = bid & 15; by = bid >> 4; }
    else if (bid < 1280) { int id = bid - 256;  in = W1; op = out + (size_t)4*1024*1024; K = EMB; N = FFD; bx = id & 63; by = id >> 6; }
    else                 { int id = bid - 1280; in = W2; op = out + (size_t)8*1024*1024; K = FFD; N = EMB; bx = id & 15; by = id >> 4; }
    int n0 = bx * 64, k0 = by * 64;
    int t = threadIdx.x;
#pragma unroll
    for (int i = 0; i < 4; i++) {
        int idx = t + i*256;
        int r = idx >> 4, c4 = (idx & 15) * 4;
        float4 v = *reinterpret_cast<const float4*>(&in[(size_t)(k0 + r)*N + n0 + c4]);
        tile[r][c4] = v.x; tile[r][c4+1] = v.y; tile[r][c4+2] = v.z; tile[r][c4+3] = v.w;
    }
    __syncthreads();
#pragma unroll
    for (int i = 0; i < 2; i++) {
        int idx = t + i*256;
        int r = idx >> 3, kc = (idx & 7) * 8;
        __half hs[8];
#pragma unroll
        for (int j = 0; j < 8; j++) hs[j] = __float2half(tile[kc + j][r]);
        *reinterpret_cast<uint4*>(&op[(size_t)(n0 + r)*K + k0 + kc]) = *reinterpret_cast<uint4*>(hs);
    }
}

__global__ void convert_vt(const __half* __restrict__ in, __half* __restrict__ out) {
    __shared__ __half tile[64][72];
    int b = blockIdx.z;
    int j0 = blockIdx.x * 64, e0 = blockIdx.y * 64;
    int t = threadIdx.x;
#pragma unroll
    for (int i = 0; i < 2; i++) {
        int idx = t + i*256;
        int r = idx >> 3, c8 = (idx & 7) * 8;
        *reinterpret_cast<uint4*>(&tile[r][c8]) =
            *reinterpret_cast<const uint4*>(&in[(size_t)(b*SEQ + j0 + r)*EMB + e0 + c8]);
    }
    __syncthreads();
#pragma unroll
    for (int i = 0; i < 2; i++) {
        int idx = t + i*256;
        int r = idx >> 3, jc = (idx & 7) * 8;
        __half hs[8];
#pragma unroll
        for (int j = 0; j < 8; j++) hs[j] = tile[jc + j][r];
        *reinterpret_cast<uint4*>(&out[(size_t)(b*EMB + e0 + r)*SEQ + j0 + jc]) = *reinterpret_cast<uint4*>(hs);
    }
}

// ================= tensor-core GEMM (fp16 x fp16 -> fp32) ==========================
// CTA tile 128x128, 4 warps of 64x64 warp tiles, BK=64 slabs, 2-buffer ring,
// ONE __syncthreads per slab (prefetch issued after the sync).
static constexpr int GROW    = 144;               // smem row stride bytes (72 halves)
static constexpr int TILE_A  = 128 * GROW;        // 18432 B
static constexpr int STAGE_B = 2 * TILE_A;        // 36864 B (A + B)
static constexpr int GEMM_DSMEM = 2 * STAGE_B;    // 73728 B

__device__ __forceinline__ void stage_load(uint32_t sdst,
        const __half* __restrict__ A, const __half* __restrict__ B,
        int m0, int n0, int K, int kk, int t) {
    // 128 threads: A 1024 16B-chunks (8/thread), B same
#pragma unroll
    for (int i = 0; i < 8; i++) {
        int id = t + i*128;
        int r  = id >> 3;
        int c8 = (id & 7) * 8;
        uint32_t soff = (uint32_t)(r * GROW + c8 * 2);
        cp_async16(sdst + soff,          A + (size_t)(m0 + r) * K + kk + c8);
        cp_async16(sdst + TILE_A + soff, B + (size_t)(n0 + r) * K + kk + c8);
    }
}

template <int MODE, bool GELU>
__global__ void __launch_bounds__(128, 2)
gemm_mma(const __half* __restrict__ A, const __half* __restrict__ B,
         const float* __restrict__ bias, const float* __restrict__ res,
         void* __restrict__ Cv, QKVPtrs P, int N, int K, float alpha)
{
    extern __shared__ char dsm[];
    const uint32_t sb = smem_u32(dsm);
    const int t = threadIdx.x, lane = t & 31, wid = t >> 5;
    const int wm = (wid & 1) * 64;
    const int wn = (wid >> 1) * 64;
    const int m0 = blockIdx.y * 128;
    const int n0 = blockIdx.x * 128;

    float acc[4][8][4];
#pragma unroll
    for (int i = 0; i < 4; i++)
#pragma unroll
        for (int j = 0; j < 8; j++)
#pragma unroll
            for (int d = 0; d < 4; d++) acc[i][j][d] = 0.f;

    const int S = K >> 6;   // BK=64 slabs

    const int arow = (lane & 7) + ((lane >> 3) & 1) * 8;
    const int akof = (lane >> 4) * 8;
    const int brow = (lane & 7) + ((lane >> 4) << 3);
    const int bkof = ((lane >> 3) & 1) * 8;

    stage_load(sb, A, B, m0, n0, K, 0, t); CP_COMMIT();

    for (int s = 0; s < S; s++) {
        CP_WAIT(0);          // stage s landed (only pending group)
        __syncthreads();     // visible to all; all warps done computing s-1
        if (s + 1 < S) {     // refill buffer (s+1)&1, consumed in slab s-1: safe
            stage_load(sb + (uint32_t)((s + 1) & 1) * STAGE_B, A, B, m0, n0, K, (s + 1) << 6, t);
            CP_COMMIT();
        }

        const uint32_t base = sb + (uint32_t)(s & 1) * STAGE_B;
#pragma unroll
        for (int ks = 0; ks < 4; ks++) {
            uint32_t bfr[4][4];
#pragma unroll
            for (int bi = 0; bi < 4; bi++)
                ldsm4(bfr[bi], base + TILE_A +
                      (uint32_t)((wn + bi*16 + brow) * GROW + (ks*16 + bkof) * 2));
#pragma unroll
            for (int mi = 0; mi < 4; mi++) {
                uint32_t af[4];
                ldsm4(af, base + (uint32_t)((wm + mi*16 + arow) * GROW + (ks*16 + akof) * 2));
#pragma unroll
                for (int nj = 0; nj < 8; nj++)
                    mma16816h(acc[mi][nj], af, &bfr[nj >> 1][(nj & 1) * 2]);
            }
        }
    }

    __half* hdst = nullptr;
    int nstride = N, ncol0 = n0;
    float alp = alpha;
    if (MODE == 2) {
        int nb = n0 >> 10;
        hdst = nb == 0 ? P.q : (nb == 1 ? P.k : P.v);
        alp = nb == 0 ? alpha : 1.0f;
        nstride = EMB;
        ncol0 = n0 & 1023;
    } else if (MODE == 1) {
        hdst = (__half*)Cv;
    }

#pragma unroll
    for (int mi = 0; mi < 4; mi++) {
#pragma unroll
        for (int half = 0; half < 2; half++) {
            int row = m0 + wm + mi*16 + (lane >> 2) + half * 8;
            const float* rrow = (MODE == 0 && res) ? res + (size_t)row * N : (const float*)nullptr;
#pragma unroll
            for (int nj = 0; nj < 8; nj++) {
                int coln = wn + nj*8 + (lane & 3) * 2;
                float vx = acc[mi][nj][half*2 + 0] * alp;
                float vy = acc[mi][nj][half*2 + 1] * alp;
                if (bias) { vx += bias[n0 + coln]; vy += bias[n0 + coln + 1]; }
                if (GELU) {
                    vx = 0.5f * vx * (1.f + erff(vx * 0.70710678118654752f));
                    vy = 0.5f * vy * (1.f + erff(vy * 0.70710678118654752f));
                }
                if (MODE == 0) {
                    int col = n0 + coln;
                    if (rrow) {
                        float2 r2 = *reinterpret_cast<const float2*>(rrow + col);
                        vx += r2.x; vy += r2.y;
                    }
                    *reinterpret_cast<float2*>((float*)Cv + (size_t)row * N + col) = make_float2(vx, vy);
                } else {
                    int col = ncol0 + coln;
                    *reinterpret_cast<__half2*>(hdst + (size_t)row * nstride + col) =
                        __halves2half2(__float2half(vx), __float2half(vy));
                }
            }
        }
    }
}

// ================= fused differential flash attention + sublayer RMS =================
// 2 syncs per chunk: WAIT -> sync -> prefetch(c+1) -> QK/P -> sync -> PV.
static constexpr int FQS = 72;
static constexpr int FA_DSMEM = 36864 + 2*36864;

__device__ __forceinline__ void fa_prefetch(uint32_t stg, const __half* __restrict__ kh,
                                            const __half* __restrict__ vt,
                                            int b, int h, int j0, int t) {
#pragma unroll
    for (int l = 0; l < 4; l++) {
        int x = t + l * 256;
        int map = x >> 9;
        int r = (x >> 3) & 63;
        int c8 = (x & 7) * 8;
        const __half* src = kh + (size_t)(b*SEQ + j0 + r) * EMB + (2*h + map)*64 + c8;
        cp_async16(stg + map*9216 + (uint32_t)(r*FQS + c8)*2, src);
    }
#pragma unroll
    for (int l = 0; l < 4; l++) {
        int x = t + l * 256;
        int r = x >> 3;
        int c8 = (x & 7) * 8;
        const __half* src = vt + (size_t)(b*EMB + h*DV + r) * SEQ + j0 + c8;
        cp_async16(stg + 18432 + (uint32_t)(r*FQS + c8)*2, src);
    }
}

__global__ void __launch_bounds__(256, 2)
flash_kernel(const __half* __restrict__ qh, const __half* __restrict__ kh,
             const __half* __restrict__ vt, const float* __restrict__ subln,
             __half* __restrict__ ao)
{
    extern __shared__ char fsm[];
    __shared__ float red_l[2][2][64];
    __shared__ float red_sq[2][64];
    const uint32_t sb = smem_u32(fsm);

    const int t = threadIdx.x, lane = t & 31, wid = t >> 5;
    const int wm = (wid & 3) * 16;
    const int wn = wid >> 2;
    const int i0 = blockIdx.x * 64;
    const int h = blockIdx.y, b = blockIdx.z;
    const float lam = g_lam;

    const int arow = (lane & 7) + ((lane >> 3) & 1) * 8;
    const int akof = (lane >> 4) * 8;
    const int brow = (lane & 7) + ((lane >> 4) << 3);
    const int bkof = ((lane >> 3) & 1) * 8;
    const int r0 = wm + (lane >> 2);

#pragma unroll
    for (int map = 0; map < 2; map++) {
        const __half* src = qh + (size_t)(b*SEQ + i0) * EMB + (2*h + map)*64;
        char* dst = fsm + map * 9216;
        for (int id = t; id < 512; id += 256) {
            int r = id >> 3, c8 = (id & 7) * 8;
            uint4 v = *reinterpret_cast<const uint4*>(src + (size_t)r * EMB + c8);
            *reinterpret_cast<uint4*>(dst + (r*FQS + c8)*2) = v;
        }
    }

    float Oacc[2][8][4];
#pragma unroll
    for (int m = 0; m < 2; m++)
#pragma unroll
        for (int f = 0; f < 8; f++)
#pragma unroll
            for (int d = 0; d < 4; d++) Oacc[m][f][d] = 0.f;
    float lst[2][2] = {{0.f, 0.f}, {0.f, 0.f}};

    fa_prefetch(sb + 36864, kh, vt, b, h, 0, t);
    CP_COMMIT();

    for (int c = 0; c < SEQ/64; c++) {
        const uint32_t cur = sb + 36864 + (uint32_t)(c & 1) * 36864;
        CP_WAIT(0);        // chunk c landed (only pending group)
        __syncthreads();   // stage visible; Q visible (c==0); all warps done PV(c-1)
        if (c + 1 < SEQ/64) {
            fa_prefetch(sb + 36864 + (uint32_t)((c+1) & 1) * 36864, kh, vt, b, h, (c+1)*64, t);
            CP_COMMIT();
        }

#pragma unroll
        for (int map = 0; map < 2; map++) {
            float sacc[4][4];
#pragma unroll
            for (int f = 0; f < 4; f++)
#pragma unroll
                for (int d = 0; d < 4; d++) sacc[f][d] = 0.f;

            const uint32_t qbase = sb + (uint32_t)map * 9216;
            const uint32_t kbase = cur + (uint32_t)map * 9216;
#pragma unroll
            for (int ks = 0; ks < 4; ks++) {
                uint32_t af[4];
                ldsm4(af, qbase + (uint32_t)((wm + arow)*FQS + ks*16 + akof)*2);
                uint32_t bf[2][4];
#pragma unroll
                for (int bi = 0; bi < 2; bi++)
                    ldsm4(bf[bi], kbase + (uint32_t)((wn*32 + bi*16 + brow)*FQS + ks*16 + bkof)*2);
#pragma unroll
                for (int nj = 0; nj < 4; nj++)
                    mma16816h(sacc[nj], af, &bf[nj >> 1][(nj & 1)*2]);
            }

            float psum[2] = {0.f, 0.f};
#pragma unroll
            for (int nj = 0; nj < 4; nj++)
#pragma unroll
                for (int d = 0; d < 4; d++) {
                    float p = __expf(sacc[nj][d] - 4.0f);
                    sacc[nj][d] = p;
                    psum[d >> 1] += p;
                }
#pragma unroll
            for (int hf = 0; hf < 2; hf++) {
                psum[hf] += __shfl_xor_sync(0xffffffffu, psum[hf], 1);
                psum[hf] += __shfl_xor_sync(0xffffffffu, psum[hf], 2);
                lst[map][hf] += psum[hf];
            }

            char* pbase = fsm + 18432 + map * 9216;
#pragma unroll
            for (int nj = 0; nj < 4; nj++)
#pragma unroll
                for (int hf = 0; hf < 2; hf++) {
                    int row = r0 + hf * 8;
                    int col = wn*32 + nj*8 + (lane & 3)*2;
                    __half2 hp = __halves2half2(__float2half(sacc[nj][hf*2]),
                                                __float2half(sacc[nj][hf*2+1]));
                    *reinterpret_cast<__half2*>(pbase + (row*FQS + col)*2) = hp;
                }
        }
        __syncthreads();   // P complete (both maps)

        // ---- fused PV: each V fragment loaded once, used by both maps ----
        {
            const uint32_t p0 = sb + 18432;
            const uint32_t p1 = sb + 18432 + 9216;
            const uint32_t vbase = cur + 18432;
#pragma unroll
            for (int ks = 0; ks < 4; ks++) {
                uint32_t af0[4], af1[4];
                uint32_t poff = (uint32_t)((wm + arow)*FQS + ks*16 + akof)*2;
                ldsm4(af0, p0 + poff);
                ldsm4(af1, p1 + poff);
#pragma unroll
                for (int bi = 0; bi < 4; bi++) {
                    uint32_t bf[4];
                    ldsm4(bf, vbase + (uint32_t)((wn*64 + bi*16 + brow)*FQS + ks*16 + bkof)*2);
                    mma16816h(Oacc[0][bi*2 + 0], af0, &bf[0]);
                    mma16816h(Oacc[0][bi*2 + 1], af0, &bf[2]);
                    mma16816h(Oacc[1][bi*2 + 0], af1, &bf[0]);
                    mma16816h(Oacc[1][bi*2 + 1], af1, &bf[2]);
                }
            }
        }
        // no trailing sync: next iteration's first sync protects P/stage reuse
    }

    __syncthreads();   // all PV done before reduction smem use
    if ((lane & 3) == 0) {
        red_l[0][wn][r0]     = lst[0][0];
        red_l[0][wn][r0 + 8] = lst[0][1];
        red_l[1][wn][r0]     = lst[1][0];
        red_l[1][wn][r0 + 8] = lst[1][1];
    }
    __syncthreads();

    float vals[2][8][2];
    float sq[2] = {0.f, 0.f};
#pragma unroll
    for (int hf = 0; hf < 2; hf++) {
        int rr = r0 + hf*8;
        float inv0 = 1.f / (red_l[0][0][rr] + red_l[0][1][rr]);
        float inv1 = 1.f / (red_l[1][0][rr] + red_l[1][1][rr]);
#pragma unroll
        for (int f = 0; f < 8; f++) {
            float vx = Oacc[0][f][hf*2+0]*inv0 - lam*Oacc[1][f][hf*2+0]*inv1;
            float vy = Oacc[0][f][hf*2+1]*inv0 - lam*Oacc[1][f][hf*2+1]*inv1;
            vals[hf][f][0] = vx; vals[hf][f][1] = vy;
            sq[hf] += vx*vx + vy*vy;
        }
    }
#pragma unroll
    for (int hf = 0; hf < 2; hf++) {
        sq[hf] += __shfl_xor_sync(0xffffffffu, sq[hf], 1);
        sq[hf] += __shfl_xor_sync(0xffffffffu, sq[hf], 2);
    }
    if ((lane & 3) == 0) {
        red_sq[wn][r0]     = sq[0];
        red_sq[wn][r0 + 8] = sq[1];
    }
    __syncthreads();

#pragma unroll
    for (int hf = 0; hf < 2; hf++) {
        int rr = r0 + hf*8;
        float tot = red_sq[0][rr] + red_sq[1][rr];
        float scale = rsqrtf(tot * (1.f/DV) + 1e-5f) * (1.f - LAM_INIT);
        int row = i0 + rr;
#pragma unroll
        for (int f = 0; f < 8; f++) {
            int cdv = wn*64 + f*8 + (lane & 3)*2;
            float2 w2 = *reinterpret_cast<const float2*>(subln + cdv);
            float vx = vals[hf][f][0] * scale * w2.x;
            float vy = vals[hf][f][1] * scale * w2.y;
            *reinterpret_cast<__half2*>(ao + (size_t)(b*SEQ + row)*EMB + h*DV + cdv) =
                __halves2half2(__float2half(vx), __float2half(vy));
        }
    }
}

// ---------------- lambda scalar ----------------
__global__ void lam_kernel(const float* __restrict__ lq1, const float* __restrict__ lk1,
                           const float* __restrict__ lq2, const float* __restrict__ lk2) {
    int t = threadIdx.x;
    float a = lq1[t]*lk1[t] + lq1[t+32]*lk1[t+32];
    float b = lq2[t]*lk2[t] + lq2[t+32]*lk2[t+32];
#pragma unroll
    for (int o = 16; o > 0; o >>= 1) {
        a += __shfl_down_sync(0xffffffffu, a, o);
        b += __shfl_down_sync(0xffffffffu, b, o);
    }
    if (t == 0) g_lam = expf(a) - expf(b) + LAM_INIT;
}

// ---------------- layernorm: fp32 in, fp16 out ----------------
__global__ void ln_kernel(const float* __restrict__ x, const float* __restrict__ w,
                          const float* __restrict__ b, __half* __restrict__ out) {
    int row = blockIdx.x;
    const float* xr = x + (size_t)row*EMB;
    int t = threadIdx.x;
    float v[4];
    float s = 0.f, ss = 0.f;
#pragma unroll
    for (int i = 0; i < 4; i++) {
        v[i] = xr[t + i*256];
        s += v[i]; ss += v[i]*v[i];
    }
    __shared__ float shs[8], shss[8];
#pragma unroll
    for (int o = 16; o > 0; o >>= 1) {
        s  += __shfl_down_sync(0xffffffffu, s,  o);
        ss += __shfl_down_sync(0xffffffffu, ss, o);
    }
    int wid = t >> 5, lane = t & 31;
    if (lane == 0) { shs[wid] = s; shss[wid] = ss; }
    __syncthreads();
    if (t == 0) {
        float a = 0.f, c = 0.f;
#pragma unroll
        for (int i = 0; i < 8; i++) { a += shs[i]; c += shss[i]; }
        shs[0] = a; shss[0] = c;
    }
    __syncthreads();
    float mean = shs[0] * (1.f/EMB);
    float var  = shss[0] * (1.f/EMB) - mean*mean;
    float r = rsqrtf(var + 1e-5f);
    __half* orow = out + (size_t)row*EMB;
#pragma unroll
    for (int i = 0; i < 4; i++) {
        int c = t + i*256;
        orow[c] = __float2half((v[i] - mean) * r * w[c] + b[c]);
    }
}

// ---------------- launch ----------------
extern "C" void kernel_launch(void* const* d_in, const int* in_sizes, int n_in,
                              void* d_out, int out_size) {
    const float* x      = (const float*)d_in[0];
    const float* ln1_w  = (const float*)d_in[1];
    const float* ln1_b  = (const float*)d_in[2];
    const float* Wq     = (const float*)d_in[3];
    const float* Wk     = (const float*)d_in[4];
    const float* Wv     = (const float*)d_in[5];
    const float* Wo     = (const float*)d_in[6];
    const float* lq1    = (const float*)d_in[7];
    const float* lk1    = (const float*)d_in[8];
    const float* lq2    = (const float*)d_in[9];
    const float* lk2    = (const float*)d_in[10];
    const float* subln  = (const float*)d_in[11];
    const float* ln2_w  = (const float*)d_in[12];
    const float* ln2_b  = (const float*)d_in[13];
    const float* W1     = (const float*)d_in[14];
    const float* b1     = (const float*)d_in[15];
    const float* W2     = (const float*)d_in[16];
    const float* b2     = (const float*)d_in[17];
    float* out = (float*)d_out;

    __half *h, *qh, *kh, *vh, *vt, *ao, *ffi, *wbuf;
    float *x1;
    cudaGetSymbolAddress((void**)&h,   g_h);
    cudaGetSymbolAddress((void**)&qh,  g_qh);
    cudaGetSymbolAddress((void**)&kh,  g_kh);
    cudaGetSymbolAddress((void**)&vh,  g_vh);
    cudaGetSymbolAddress((void**)&vt,  g_vt);
    cudaGetSymbolAddress((void**)&ao,  g_ao);
    cudaGetSymbolAddress((void**)&ffi, g_t);
    cudaGetSymbolAddress((void**)&wbuf,g_w);
    cudaGetSymbolAddress((void**)&x1,  g_x1);

    cudaFuncSetAttribute(gemm_mma<0,false>, cudaFuncAttributeMaxDynamicSharedMemorySize, GEMM_DSMEM);
    cudaFuncSetAttribute(gemm_mma<1,true>,  cudaFuncAttributeMaxDynamicSharedMemorySize, GEMM_DSMEM);
    cudaFuncSetAttribute(gemm_mma<2,false>, cudaFuncAttributeMaxDynamicSharedMemorySize, GEMM_DSMEM);
    cudaFuncSetAttribute(flash_kernel,      cudaFuncAttributeMaxDynamicSharedMemorySize, FA_DSMEM);

    QKVPtrs qkv = {qh, kh, vh};
    QKVPtrs nop = {nullptr, nullptr, nullptr};

    const __half* wqkv = wbuf;
    const __half* wo   = wbuf + (size_t)3*1024*1024;
    const __half* w1h  = wbuf + (size_t)4*1024*1024;
    const __half* w2h  = wbuf + (size_t)8*1024*1024;

    lam_kernel<<<1, 32>>>(lq1, lk1, lq2, lk2);

    convert_tr3<<<dim3(16, 16, 3), 256>>>(Wq, Wk, Wv, wbuf);
    convert_w_all<<<2304, 256>>>(Wo, W1, W2, wbuf);

    ln_kernel<<<ROWS, 256>>>(x, ln1_w, ln1_b, h);

    // fused QKV GEMM (N=3072, q pre-scaled by 0.125)
    gemm_mma<2,false><<<dim3(3*EMB/128, ROWS/128), 128, GEMM_DSMEM>>>(
        h, wqkv, nullptr, nullptr, nullptr, qkv, 3*EMB, EMB, 0.125f);

    convert_vt<<<dim3(SEQ/64, EMB/64, BATCH), 256>>>(vh, vt);

    flash_kernel<<<dim3(SEQ/64, NHEAD, BATCH), 256, FA_DSMEM>>>(qh, kh, vt, subln, ao);

    // x1 = x + ao @ Wo (fp32)
    gemm_mma<0,false><<<dim3(EMB/128, ROWS/128), 128, GEMM_DSMEM>>>(
        ao, wo, nullptr, x, x1, nop, EMB, EMB, 1.0f);

    ln_kernel<<<ROWS, 256>>>(x1, ln2_w, ln2_b, h);
    gemm_mma<1,true><<<dim3(FFD/128, ROWS/128), 128, GEMM_DSMEM>>>(
        h, w1h, b1, nullptr, ffi, nop, FFD, EMB, 1.0f);

    gemm_mma<0,false><<<dim3(EMB/128, ROWS/128), 128, GEMM_DSMEM>>>(
        ffi, w2h, b2, x1, out, nop, EMB, FFD, 1.0f);
}

// round 15
// speedup vs baseline: 1.0225x; 1.0225x over previous
#include <cuda_runtime.h>
#include <cuda_fp16.h>
#include <math.h>
#include <cstdint>

// ---------------- problem constants ----------------
#define EMB   1024
#define NHEAD 8
#define HDIM  64
#define NH2   16
#define DV    128
#define FFD   4096
#define BATCH 2
#define SEQ   2048
#define ROWS  (BATCH*SEQ)
#define LAM_INIT 0.35550906759096926f

// ---------------- device scratch ----------------
__device__ __half g_h [ROWS*EMB];
__device__ __half g_qh[(size_t)ROWS*EMB];
__device__ __half g_kh[(size_t)ROWS*EMB];
__device__ __half g_vh[(size_t)ROWS*EMB];
__device__ __half g_ao[(size_t)ROWS*EMB];
__device__ __half g_t [(size_t)ROWS*FFD];
__device__ __half g_w [(size_t)12*1024*1024];  // weight arena: QKV@0, Wo@3M, W1@4M, W2@8M
__device__ float  g_x1[ROWS*EMB];
__device__ float  g_lam;

struct QKVPtrs { __half* q; __half* k; __half* v; };

// ================= baseline-PTX helpers =================
__device__ __forceinline__ uint32_t smem_u32(const void* p) {
    uint32_t a;
    asm("{ .reg .u64 t; cvta.to.shared.u64 t, %1; cvt.u32.u64 %0, t; }" : "=r"(a) : "l"(p));
    return a;
}

__device__ __forceinline__ void cp_async16(uint32_t dst, const void* src) {
    asm volatile("cp.async.cg.shared.global [%0], [%1], 16;" :: "r"(dst), "l"(src));
}
#define CP_COMMIT() asm volatile("cp.async.commit_group;" ::: "memory")
#define CP_WAIT(n)  asm volatile("cp.async.wait_group %0;" :: "n"(n) : "memory")

__device__ __forceinline__ void ldsm4(uint32_t* r, uint32_t addr) {
    asm volatile("ldmatrix.sync.aligned.m8n8.x4.shared.b16 {%0,%1,%2,%3}, [%4];"
        : "=r"(r[0]), "=r"(r[1]), "=r"(r[2]), "=r"(r[3]) : "r"(addr));
}

__device__ __forceinline__ void ldsm4t(uint32_t* r, uint32_t addr) {
    asm volatile("ldmatrix.sync.aligned.m8n8.x4.trans.shared.b16 {%0,%1,%2,%3}, [%4];"
        : "=r"(r[0]), "=r"(r[1]), "=r"(r[2]), "=r"(r[3]) : "r"(addr));
}

__device__ __forceinline__ void mma16816h(float* d, const uint32_t* a, const uint32_t* b) {
    asm volatile("mma.sync.aligned.m16n8k16.row.col.f32.f16.f16.f32 "
        "{%0,%1,%2,%3}, {%4,%5,%6,%7}, {%8,%9}, {%0,%1,%2,%3};"
        : "+f"(d[0]), "+f"(d[1]), "+f"(d[2]), "+f"(d[3])
        : "r"(a[0]), "r"(a[1]), "r"(a[2]), "r"(a[3]), "r"(b[0]), "r"(b[1]));
}

// ================= conversion kernels (vectorized, 64x64 tiles) =================
__global__ void convert_tr3(const float* __restrict__ w0, const float* __restrict__ w1,
                            const float* __restrict__ w2, __half* __restrict__ out) {
    __shared__ float tile[64][65];
    const float* in = blockIdx.z == 0 ? w0 : (blockIdx.z == 1 ? w1 : w2);
    __half* op = out + (size_t)blockIdx.z * EMB * EMB;
    int n0 = blockIdx.x * 64, k0 = blockIdx.y * 64;
    int t = threadIdx.x;
#pragma unroll
    for (int i = 0; i < 4; i++) {
        int idx = t + i*256;
        int r = idx >> 4, c4 = (idx & 15) * 4;
        float4 v = *reinterpret_cast<const float4*>(&in[(size_t)(k0 + r)*EMB + n0 + c4]);
        tile[r][c4] = v.x; tile[r][c4+1] = v.y; tile[r][c4+2] = v.z; tile[r][c4+3] = v.w;
    }
    __syncthreads();
#pragma unroll
    for (int i = 0; i < 2; i++) {
        int idx = t + i*256;
        int r = idx >> 3, kc = (idx & 7) * 8;
        __half hs[8];
#pragma unroll
        for (int j = 0; j < 8; j++) hs[j] = __float2half(tile[kc + j][r]);
        *reinterpret_cast<uint4*>(&op[(size_t)(n0 + r)*EMB + k0 + kc]) = *reinterpret_cast<uint4*>(hs);
    }
}

__global__ void convert_w_all(const float* __restrict__ Wo, const float* __restrict__ W1,
                              const float* __restrict__ W2, __half* __restrict__ out) {
    __shared__ float tile[64][65];
    int bid = blockIdx.x;
    const float* in; __half* op; int K, N, bx, by;
    if (bid < 256)       { in = Wo; op = out + (size_t)3*1024*1024; K = EMB; N = EMB; bx = bid & 15; by = bid >> 4; }
    else if (bid < 1280) { int id = bid - 256;  in = W1; op = out + (size_t)4*1024*1024; K = EMB; N = FFD; bx = id & 63; by = id >> 6; }
    else                 { int id = bid - 1280; in = W2; op = out + (size_t)8*1024*1024; K = FFD; N = EMB; bx = id & 15; by = id >> 4; }
    int n0 = bx * 64, k0 = by * 64;
    int t = threadIdx.x;
#pragma unroll
    for (int i = 0; i < 4; i++) {
        int idx = t + i*256;
        int r = idx >> 4, c4 = (idx & 15) * 4;
        float4 v = *reinterpret_cast<const float4*>(&in[(size_t)(k0 + r)*N + n0 + c4]);
        tile[r][c4] = v.x; tile[r][c4+1] = v.y; tile[r][c4+2] = v.z; tile[r][c4+3] = v.w;
    }
    __syncthreads();
#pragma unroll
    for (int i = 0; i < 2; i++) {
        int idx = t + i*256;
        int r = idx >> 3, kc = (idx & 7) * 8;
        __half hs[8];
#pragma unroll
        for (int j = 0; j < 8; j++) hs[j] = __float2half(tile[kc + j][r]);
        *reinterpret_cast<uint4*>(&op[(size_t)(n0 + r)*K + k0 + kc]) = *reinterpret_cast<uint4*>(hs);
    }
}

// ================= tensor-core GEMM (fp16 x fp16 -> fp32) ==========================
// R13 config: CTA 128x128, 4 warps of 64x64 warp tiles, BK=32, 3-stage ring.
static constexpr int TILE_A   = 128 * 80;
static constexpr int TILE_BB  = 128 * 80;
static constexpr int STAGE_B  = TILE_A + TILE_BB;  // 20480 B
static constexpr int GEMM_DSMEM = 3 * STAGE_B;     // 61440 B

__device__ __forceinline__ void stage_load(uint32_t sdst,
        const __half* __restrict__ A, const __half* __restrict__ B,
        int m0, int n0, int K, int kk, int t) {
#pragma unroll
    for (int i = 0; i < 4; i++) {
        int id = t + i*128;
        int r  = id >> 2;
        int c8 = (id & 3) * 8;
        uint32_t soff = (uint32_t)(r * 80 + c8 * 2);
        cp_async16(sdst + soff,          A + (size_t)(m0 + r) * K + kk + c8);
        cp_async16(sdst + TILE_A + soff, B + (size_t)(n0 + r) * K + kk + c8);
    }
}

template <int MODE, bool GELU>
__global__ void __launch_bounds__(128, 2)
gemm_mma(const __half* __restrict__ A, const __half* __restrict__ B,
         const float* __restrict__ bias, const float* __restrict__ res,
         void* __restrict__ Cv, QKVPtrs P, int N, int K, float alpha)
{
    extern __shared__ char dsm[];
    const uint32_t sb = smem_u32(dsm);
    const int t = threadIdx.x, lane = t & 31, wid = t >> 5;
    const int wm = (wid & 1) * 64;
    const int wn = (wid >> 1) * 64;
    const int m0 = blockIdx.y * 128;
    const int n0 = blockIdx.x * 128;

    float acc[4][8][4];
#pragma unroll
    for (int i = 0; i < 4; i++)
#pragma unroll
        for (int j = 0; j < 8; j++)
#pragma unroll
            for (int d = 0; d < 4; d++) acc[i][j][d] = 0.f;

    const int S = K >> 5;

    const int arow = (lane & 7) + ((lane >> 3) & 1) * 8;
    const int akof = (lane >> 4) * 8;
    const int brow = (lane & 7) + ((lane >> 4) << 3);
    const int bkof = ((lane >> 3) & 1) * 8;

    stage_load(sb,           A, B, m0, n0, K, 0,  t); CP_COMMIT();
    stage_load(sb + STAGE_B, A, B, m0, n0, K, 32, t); CP_COMMIT();

    int buf = 0;
    for (int s = 0; s < S; s++) {
        CP_WAIT(1);
        __syncthreads();
        if (s + 2 < S) {
            int nb = buf + 2; if (nb >= 3) nb -= 3;
            stage_load(sb + (uint32_t)nb * STAGE_B, A, B, m0, n0, K, (s + 2) << 5, t);
        }
        CP_COMMIT();

        const uint32_t base = sb + (uint32_t)buf * STAGE_B;
#pragma unroll
        for (int ks = 0; ks < 2; ks++) {
            uint32_t bfr[4][4];
#pragma unroll
            for (int bi = 0; bi < 4; bi++)
                ldsm4(bfr[bi], base + TILE_A +
                      (uint32_t)((wn + bi*16 + brow) * 80 + (ks*16 + bkof) * 2));
#pragma unroll
            for (int mi = 0; mi < 4; mi++) {
                uint32_t af[4];
                ldsm4(af, base + (uint32_t)((wm + mi*16 + arow) * 80 + (ks*16 + akof) * 2));
#pragma unroll
                for (int nj = 0; nj < 8; nj++)
                    mma16816h(acc[mi][nj], af, &bfr[nj >> 1][(nj & 1) * 2]);
            }
        }
        if (++buf == 3) buf = 0;
    }

    __half* hdst = nullptr;
    int nstride = N, ncol0 = n0;
    float alp = alpha;
    if (MODE == 2) {
        int nb = n0 >> 10;
        hdst = nb == 0 ? P.q : (nb == 1 ? P.k : P.v);
        alp = nb == 0 ? alpha : 1.0f;
        nstride = EMB;
        ncol0 = n0 & 1023;
    } else if (MODE == 1) {
        hdst = (__half*)Cv;
    }

#pragma unroll
    for (int mi = 0; mi < 4; mi++) {
#pragma unroll
        for (int half = 0; half < 2; half++) {
            int row = m0 + wm + mi*16 + (lane >> 2) + half * 8;
            const float* rrow = (MODE == 0 && res) ? res + (size_t)row * N : (const float*)nullptr;
#pragma unroll
            for (int nj = 0; nj < 8; nj++) {
                int coln = wn + nj*8 + (lane & 3) * 2;
                float vx = acc[mi][nj][half*2 + 0] * alp;
                float vy = acc[mi][nj][half*2 + 1] * alp;
                if (bias) { vx += bias[n0 + coln]; vy += bias[n0 + coln + 1]; }
                if (GELU) {
                    vx = 0.5f * vx * (1.f + erff(vx * 0.70710678118654752f));
                    vy = 0.5f * vy * (1.f + erff(vy * 0.70710678118654752f));
                }
                if (MODE == 0) {
                    int col = n0 + coln;
                    if (rrow) {
                        float2 r2 = *reinterpret_cast<const float2*>(rrow + col);
                        vx += r2.x; vy += r2.y;
                    }
                    *reinterpret_cast<float2*>((float*)Cv + (size_t)row * N + col) = make_float2(vx, vy);
                } else {
                    int col = ncol0 + coln;
                    *reinterpret_cast<__half2*>(hdst + (size_t)row * nstride + col) =
                        __halves2half2(__float2half(vx), __float2half(vy));
                }
            }
        }
    }
}

// ================= fused differential flash attention + sublayer RMS =================
// V loaded untransposed from vh; PV B-fragments via ldmatrix.trans (no vt buffer).
// 2 syncs per chunk. Stage: K0@0 (9216), K1@9216 (9216), V@18432 (64 x 272 = 17408).
static constexpr int FQS = 72;      // K/Q/P row stride (halves)
static constexpr int VRS = 272;     // V row stride (bytes)
static constexpr int FA_STAGE = 36864;
static constexpr int FA_DSMEM = 36864 + 2*FA_STAGE;

__device__ __forceinline__ void fa_prefetch(uint32_t stg, const __half* __restrict__ kh,
                                            const __half* __restrict__ vh,
                                            int b, int h, int j0, int t) {
#pragma unroll
    for (int l = 0; l < 4; l++) {       // K both maps: 1024 chunks
        int x = t + l * 256;
        int map = x >> 9;
        int r = (x >> 3) & 63;
        int c8 = (x & 7) * 8;
        const __half* src = kh + (size_t)(b*SEQ + j0 + r) * EMB + (2*h + map)*64 + c8;
        cp_async16(stg + map*9216 + (uint32_t)(r*FQS + c8)*2, src);
    }
#pragma unroll
    for (int l = 0; l < 4; l++) {       // V rows: 64 x 128 halves = 1024 chunks
        int x = t + l * 256;
        int r = x >> 4;                 // 0..63 (j)
        int c8 = (x & 15) * 8;          // 0..120 (e)
        const __half* src = vh + (size_t)(b*SEQ + j0 + r) * EMB + h*DV + c8;
        cp_async16(stg + 18432 + (uint32_t)(r*VRS + c8*2), src);
    }
}

__global__ void __launch_bounds__(256, 2)
flash_kernel(const __half* __restrict__ qh, const __half* __restrict__ kh,
             const __half* __restrict__ vh, const float* __restrict__ subln,
             __half* __restrict__ ao)
{
    extern __shared__ char fsm[];
    __shared__ float red_l[2][2][64];
    __shared__ float red_sq[2][64];
    const uint32_t sb = smem_u32(fsm);

    const int t = threadIdx.x, lane = t & 31, wid = t >> 5;
    const int wm = (wid & 3) * 16;
    const int wn = wid >> 2;
    const int i0 = blockIdx.x * 64;
    const int h = blockIdx.y, b = blockIdx.z;
    const float lam = g_lam;

    const int arow = (lane & 7) + ((lane >> 3) & 1) * 8;
    const int akof = (lane >> 4) * 8;
    const int brow = (lane & 7) + ((lane >> 4) << 3);
    const int bkof = ((lane >> 3) & 1) * 8;
    // trans ldsm lane mapping (V [j][e] -> B fragment [e][j])
    const int tkrow = (lane & 7) + ((lane >> 3) & 1) * 8;
    const int tncol = ((lane >> 4) & 1) * 8;
    const int r0 = wm + (lane >> 2);

#pragma unroll
    for (int map = 0; map < 2; map++) {
        const __half* src = qh + (size_t)(b*SEQ + i0) * EMB + (2*h + map)*64;
        char* dst = fsm + map * 9216;
        for (int id = t; id < 512; id += 256) {
            int r = id >> 3, c8 = (id & 7) * 8;
            uint4 v = *reinterpret_cast<const uint4*>(src + (size_t)r * EMB + c8);
            *reinterpret_cast<uint4*>(dst + (r*FQS + c8)*2) = v;
        }
    }

    float Oacc[2][8][4];
#pragma unroll
    for (int m = 0; m < 2; m++)
#pragma unroll
        for (int f = 0; f < 8; f++)
#pragma unroll
            for (int d = 0; d < 4; d++) Oacc[m][f][d] = 0.f;
    float lst[2][2] = {{0.f, 0.f}, {0.f, 0.f}};

    fa_prefetch(sb + 36864, kh, vh, b, h, 0, t);
    CP_COMMIT();

    for (int c = 0; c < SEQ/64; c++) {
        const uint32_t cur = sb + 36864 + (uint32_t)(c & 1) * FA_STAGE;
        CP_WAIT(0);
        __syncthreads();   // stage visible; Q visible (c==0); all warps done PV(c-1)
        if (c + 1 < SEQ/64) {
            fa_prefetch(sb + 36864 + (uint32_t)((c+1) & 1) * FA_STAGE, kh, vh, b, h, (c+1)*64, t);
            CP_COMMIT();
        }

#pragma unroll
        for (int map = 0; map < 2; map++) {
            float sacc[4][4];
#pragma unroll
            for (int f = 0; f < 4; f++)
#pragma unroll
                for (int d = 0; d < 4; d++) sacc[f][d] = 0.f;

            const uint32_t qbase = sb + (uint32_t)map * 9216;
            const uint32_t kbase = cur + (uint32_t)map * 9216;
#pragma unroll
            for (int ks = 0; ks < 4; ks++) {
                uint32_t af[4];
                ldsm4(af, qbase + (uint32_t)((wm + arow)*FQS + ks*16 + akof)*2);
                uint32_t bf[2][4];
#pragma unroll
                for (int bi = 0; bi < 2; bi++)
                    ldsm4(bf[bi], kbase + (uint32_t)((wn*32 + bi*16 + brow)*FQS + ks*16 + bkof)*2);
#pragma unroll
                for (int nj = 0; nj < 4; nj++)
                    mma16816h(sacc[nj], af, &bf[nj >> 1][(nj & 1)*2]);
            }

            float psum[2] = {0.f, 0.f};
#pragma unroll
            for (int nj = 0; nj < 4; nj++)
#pragma unroll
                for (int d = 0; d < 4; d++) {
                    float p = __expf(sacc[nj][d] - 4.0f);
                    sacc[nj][d] = p;
                    psum[d >> 1] += p;
                }
#pragma unroll
            for (int hf = 0; hf < 2; hf++) {
                psum[hf] += __shfl_xor_sync(0xffffffffu, psum[hf], 1);
                psum[hf] += __shfl_xor_sync(0xffffffffu, psum[hf], 2);
                lst[map][hf] += psum[hf];
            }

            char* pbase = fsm + 18432 + map * 9216;
#pragma unroll
            for (int nj = 0; nj < 4; nj++)
#pragma unroll
                for (int hf = 0; hf < 2; hf++) {
                    int row = r0 + hf * 8;
                    int col = wn*32 + nj*8 + (lane & 3)*2;
                    __half2 hp = __halves2half2(__float2half(sacc[nj][hf*2]),
                                                __float2half(sacc[nj][hf*2+1]));
                    *reinterpret_cast<__half2*>(pbase + (row*FQS + col)*2) = hp;
                }
        }
        __syncthreads();   // P complete (both maps)

        // ---- fused PV: V fragments via trans ldsm, loaded once, fed to both maps ----
        {
            const uint32_t p0 = sb + 18432;
            const uint32_t p1 = sb + 18432 + 9216;
            const uint32_t vbase = cur + 18432;
#pragma unroll
            for (int ks = 0; ks < 4; ks++) {
                uint32_t af0[4], af1[4];
                uint32_t poff = (uint32_t)((wm + arow)*FQS + ks*16 + akof)*2;
                ldsm4(af0, p0 + poff);
                ldsm4(af1, p1 + poff);
#pragma unroll
                for (int bi = 0; bi < 4; bi++) {
                    uint32_t bf[4];
                    ldsm4t(bf, vbase + (uint32_t)((ks*16 + tkrow)*VRS
                                                  + (wn*64 + bi*16 + tncol)*2));
                    mma16816h(Oacc[0][bi*2 + 0], af0, &bf[0]);
                    mma16816h(Oacc[0][bi*2 + 1], af0, &bf[2]);
                    mma16816h(Oacc[1][bi*2 + 0], af1, &bf[0]);
                    mma16816h(Oacc[1][bi*2 + 1], af1, &bf[2]);
                }
            }
        }
        // no trailing sync: next iteration's first sync protects P/stage reuse
    }

    __syncthreads();
    if ((lane & 3) == 0) {
        red_l[0][wn][r0]     = lst[0][0];
        red_l[0][wn][r0 + 8] = lst[0][1];
        red_l[1][wn][r0]     = lst[1][0];
        red_l[1][wn][r0 + 8] = lst[1][1];
    }
    __syncthreads();

    float vals[2][8][2];
    float sq[2] = {0.f, 0.f};
#pragma unroll
    for (int hf = 0; hf < 2; hf++) {
        int rr = r0 + hf*8;
        float inv0 = 1.f / (red_l[0][0][rr] + red_l[0][1][rr]);
        float inv1 = 1.f / (red_l[1][0][rr] + red_l[1][1][rr]);
#pragma unroll
        for (int f = 0; f < 8; f++) {
            float vx = Oacc[0][f][hf*2+0]*inv0 - lam*Oacc[1][f][hf*2+0]*inv1;
            float vy = Oacc[0][f][hf*2+1]*inv0 - lam*Oacc[1][f][hf*2+1]*inv1;
            vals[hf][f][0] = vx; vals[hf][f][1] = vy;
            sq[hf] += vx*vx + vy*vy;
        }
    }
#pragma unroll
    for (int hf = 0; hf < 2; hf++) {
        sq[hf] += __shfl_xor_sync(0xffffffffu, sq[hf], 1);
        sq[hf] += __shfl_xor_sync(0xffffffffu, sq[hf], 2);
    }
    if ((lane & 3) == 0) {
        red_sq[wn][r0]     = sq[0];
        red_sq[wn][r0 + 8] = sq[1];
    }
    __syncthreads();

#pragma unroll
    for (int hf = 0; hf < 2; hf++) {
        int rr = r0 + hf*8;
        float tot = red_sq[0][rr] + red_sq[1][rr];
        float scale = rsqrtf(tot * (1.f/DV) + 1e-5f) * (1.f - LAM_INIT);
        int row = i0 + rr;
#pragma unroll
        for (int f = 0; f < 8; f++) {
            int cdv = wn*64 + f*8 + (lane & 3)*2;
            float2 w2 = *reinterpret_cast<const float2*>(subln + cdv);
            float vx = vals[hf][f][0] * scale * w2.x;
            float vy = vals[hf][f][1] * scale * w2.y;
            *reinterpret_cast<__half2*>(ao + (size_t)(b*SEQ + row)*EMB + h*DV + cdv) =
                __halves2half2(__float2half(vx), __float2half(vy));
        }
    }
}

// ---------------- lambda scalar ----------------
__global__ void lam_kernel(const float* __restrict__ lq1, const float* __restrict__ lk1,
                           const float* __restrict__ lq2, const float* __restrict__ lk2) {
    int t = threadIdx.x;
    float a = lq1[t]*lk1[t] + lq1[t+32]*lk1[t+32];
    float b = lq2[t]*lk2[t] + lq2[t+32]*lk2[t+32];
#pragma unroll
    for (int o = 16; o > 0; o >>= 1) {
        a += __shfl_down_sync(0xffffffffu, a, o);
        b += __shfl_down_sync(0xffffffffu, b, o);
    }
    if (t == 0) g_lam = expf(a) - expf(b) + LAM_INIT;
}

// ---------------- layernorm: fp32 in, fp16 out ----------------
__global__ void ln_kernel(const float* __restrict__ x, const float* __restrict__ w,
                          const float* __restrict__ b, __half* __restrict__ out) {
    int row = blockIdx.x;
    const float* xr = x + (size_t)row*EMB;
    int t = threadIdx.x;
    float v[4];
    float s = 0.f, ss = 0.f;
#pragma unroll
    for (int i = 0; i < 4; i++) {
        v[i] = xr[t + i*256];
        s += v[i]; ss += v[i]*v[i];
    }
    __shared__ float shs[8], shss[8];
#pragma unroll
    for (int o = 16; o > 0; o >>= 1) {
        s  += __shfl_down_sync(0xffffffffu, s,  o);
        ss += __shfl_down_sync(0xffffffffu, ss, o);
    }
    int wid = t >> 5, lane = t & 31;
    if (lane == 0) { shs[wid] = s; shss[wid] = ss; }
    __syncthreads();
    if (t == 0) {
        float a = 0.f, c = 0.f;
#pragma unroll
        for (int i = 0; i < 8; i++) { a += shs[i]; c += shss[i]; }
        shs[0] = a; shss[0] = c;
    }
    __syncthreads();
    float mean = shs[0] * (1.f/EMB);
    float var  = shss[0] * (1.f/EMB) - mean*mean;
    float r = rsqrtf(var + 1e-5f);
    __half* orow = out + (size_t)row*EMB;
#pragma unroll
    for (int i = 0; i < 4; i++) {
        int c = t + i*256;
        orow[c] = __float2half((v[i] - mean) * r * w[c] + b[c]);
    }
}

// ---------------- launch ----------------
extern "C" void kernel_launch(void* const* d_in, const int* in_sizes, int n_in,
                              void* d_out, int out_size) {
    const float* x      = (const float*)d_in[0];
    const float* ln1_w  = (const float*)d_in[1];
    const float* ln1_b  = (const float*)d_in[2];
    const float* Wq     = (const float*)d_in[3];
    const float* Wk     = (const float*)d_in[4];
    const float* Wv     = (const float*)d_in[5];
    const float* Wo     = (const float*)d_in[6];
    const float* lq1    = (const float*)d_in[7];
    const float* lk1    = (const float*)d_in[8];
    const float* lq2    = (const float*)d_in[9];
    const float* lk2    = (const float*)d_in[10];
    const float* subln  = (const float*)d_in[11];
    const float* ln2_w  = (const float*)d_in[12];
    const float* ln2_b  = (const float*)d_in[13];
    const float* W1     = (const float*)d_in[14];
    const float* b1     = (const float*)d_in[15];
    const float* W2     = (const float*)d_in[16];
    const float* b2     = (const float*)d_in[17];
    float* out = (float*)d_out;

    __half *h, *qh, *kh, *vh, *ao, *ffi, *wbuf;
    float *x1;
    cudaGetSymbolAddress((void**)&h,   g_h);
    cudaGetSymbolAddress((void**)&qh,  g_qh);
    cudaGetSymbolAddress((void**)&kh,  g_kh);
    cudaGetSymbolAddress((void**)&vh,  g_vh);
    cudaGetSymbolAddress((void**)&ao,  g_ao);
    cudaGetSymbolAddress((void**)&ffi, g_t);
    cudaGetSymbolAddress((void**)&wbuf,g_w);
    cudaGetSymbolAddress((void**)&x1,  g_x1);

    cudaFuncSetAttribute(gemm_mma<0,false>, cudaFuncAttributeMaxDynamicSharedMemorySize, GEMM_DSMEM);
    cudaFuncSetAttribute(gemm_mma<1,true>,  cudaFuncAttributeMaxDynamicSharedMemorySize, GEMM_DSMEM);
    cudaFuncSetAttribute(gemm_mma<2,false>, cudaFuncAttributeMaxDynamicSharedMemorySize, GEMM_DSMEM);
    cudaFuncSetAttribute(flash_kernel,      cudaFuncAttributeMaxDynamicSharedMemorySize, FA_DSMEM);

    QKVPtrs qkv = {qh, kh, vh};
    QKVPtrs nop = {nullptr, nullptr, nullptr};

    const __half* wqkv = wbuf;
    const __half* wo   = wbuf + (size_t)3*1024*1024;
    const __half* w1h  = wbuf + (size_t)4*1024*1024;
    const __half* w2h  = wbuf + (size_t)8*1024*1024;

    lam_kernel<<<1, 32>>>(lq1, lk1, lq2, lk2);

    convert_tr3<<<dim3(16, 16, 3), 256>>>(Wq, Wk, Wv, wbuf);
    convert_w_all<<<2304, 256>>>(Wo, W1, W2, wbuf);

    ln_kernel<<<ROWS, 256>>>(x, ln1_w, ln1_b, h);

    // fused QKV GEMM (N=3072, q pre-scaled by 0.125)
    gemm_mma<2,false><<<dim3(3*EMB/128, ROWS/128), 128, GEMM_DSMEM>>>(
        h, wqkv, nullptr, nullptr, nullptr, qkv, 3*EMB, EMB, 0.125f);

    // fused differential flash attention + RMS -> ao (V read untransposed)
    flash_kernel<<<dim3(SEQ/64, NHEAD, BATCH), 256, FA_DSMEM>>>(qh, kh, vh, subln, ao);

    // x1 = x + ao @ Wo (fp32)
    gemm_mma<0,false><<<dim3(EMB/128, ROWS/128), 128, GEMM_DSMEM>>>(
        ao, wo, nullptr, x, x1, nop, EMB, EMB, 1.0f);

    ln_kernel<<<ROWS, 256>>>(x1, ln2_w, ln2_b, h);
    gemm_mma<1,true><<<dim3(FFD/128, ROWS/128), 128, GEMM_DSMEM>>>(
        h, w1h, b1, nullptr, ffi, nop, FFD, EMB, 1.0f);

    gemm_mma<0,false><<<dim3(EMB/128, ROWS/128), 128, GEMM_DSMEM>>>(
        ffi, w2h, b2, x1, out, nop, EMB, FFD, 1.0f);
}

// round 16
// speedup vs baseline: 1.0254x; 1.0029x over previous
#include <cuda_runtime.h>
#include <cuda_fp16.h>
#include <math.h>
#include <cstdint>

// ---------------- problem constants ----------------
#define EMB   1024
#define NHEAD 8
#define HDIM  64
#define NH2   16
#define DV    128
#define FFD   4096
#define BATCH 2
#define SEQ   2048
#define ROWS  (BATCH*SEQ)
#define LAM_INIT 0.35550906759096926f

// ---------------- device scratch ----------------
__device__ __half g_h [ROWS*EMB];
__device__ __half g_qh[(size_t)ROWS*EMB];
__device__ __half g_kh[(size_t)ROWS*EMB];
__device__ __half g_vh[(size_t)ROWS*EMB];
__device__ __half g_ao[(size_t)ROWS*EMB];
__device__ __half g_t [(size_t)ROWS*FFD];
__device__ __half g_w [(size_t)12*1024*1024];  // arena: QKV@0, Wo@3M, W1@4M, W2@8M
__device__ float  g_x1[ROWS*EMB];
__device__ float  g_lam;

struct QKVPtrs { __half* q; __half* k; __half* v; };

// ================= baseline-PTX helpers =================
__device__ __forceinline__ uint32_t smem_u32(const void* p) {
    uint32_t a;
    asm("{ .reg .u64 t; cvta.to.shared.u64 t, %1; cvt.u32.u64 %0, t; }" : "=r"(a) : "l"(p));
    return a;
}

__device__ __forceinline__ void cp_async16(uint32_t dst, const void* src) {
    asm volatile("cp.async.cg.shared.global [%0], [%1], 16;" :: "r"(dst), "l"(src));
}
#define CP_COMMIT() asm volatile("cp.async.commit_group;" ::: "memory")
#define CP_WAIT(n)  asm volatile("cp.async.wait_group %0;" :: "n"(n) : "memory")

__device__ __forceinline__ void ldsm4(uint32_t* r, uint32_t addr) {
    asm volatile("ldmatrix.sync.aligned.m8n8.x4.shared.b16 {%0,%1,%2,%3}, [%4];"
        : "=r"(r[0]), "=r"(r[1]), "=r"(r[2]), "=r"(r[3]) : "r"(addr));
}

__device__ __forceinline__ void ldsm4t(uint32_t* r, uint32_t addr) {
    asm volatile("ldmatrix.sync.aligned.m8n8.x4.trans.shared.b16 {%0,%1,%2,%3}, [%4];"
        : "=r"(r[0]), "=r"(r[1]), "=r"(r[2]), "=r"(r[3]) : "r"(addr));
}

__device__ __forceinline__ void mma16816h(float* d, const uint32_t* a, const uint32_t* b) {
    asm volatile("mma.sync.aligned.m16n8k16.row.col.f32.f16.f16.f32 "
        "{%0,%1,%2,%3}, {%4,%5,%6,%7}, {%8,%9}, {%0,%1,%2,%3};"
        : "+f"(d[0]), "+f"(d[1]), "+f"(d[2]), "+f"(d[3])
        : "r"(a[0]), "r"(a[1]), "r"(a[2]), "r"(a[3]), "r"(b[0]), "r"(b[1]));
}

// ================= weight conversion: ALL weights, one launch =================
// blocks 0..767: Wq/Wk/Wv -> arena@0 as [3*EMB, EMB]
// 768..1023: Wo -> @3M; 1024..2047: W1 -> @4M; 2048..3071: W2 -> @8M
__global__ void convert_w_all(const float* __restrict__ Wq, const float* __restrict__ Wk,
                              const float* __restrict__ Wv, const float* __restrict__ Wo,
                              const float* __restrict__ W1, const float* __restrict__ W2,
                              __half* __restrict__ out) {
    __shared__ float tile[64][65];
    int bid = blockIdx.x;
    const float* in; __half* op; int K, N, bx, by;
    if (bid < 768) {
        int wsel = bid >> 8, id = bid & 255;
        in = wsel == 0 ? Wq : (wsel == 1 ? Wk : Wv);
        op = out + (size_t)wsel * EMB * EMB;
        K = EMB; N = EMB; bx = id & 15; by = id >> 4;
    } else if (bid < 1024) {
        int id = bid - 768;  in = Wo; op = out + (size_t)3*1024*1024; K = EMB; N = EMB; bx = id & 15; by = id >> 4;
    } else if (bid < 2048) {
        int id = bid - 1024; in = W1; op = out + (size_t)4*1024*1024; K = EMB; N = FFD; bx = id & 63; by = id >> 6;
    } else {
        int id = bid - 2048; in = W2; op = out + (size_t)8*1024*1024; K = FFD; N = EMB; bx = id & 15; by = id >> 4;
    }
    int n0 = bx * 64, k0 = by * 64;
    int t = threadIdx.x;
#pragma unroll
    for (int i = 0; i < 4; i++) {
        int idx = t + i*256;
        int r = idx >> 4, c4 = (idx & 15) * 4;
        float4 v = *reinterpret_cast<const float4*>(&in[(size_t)(k0 + r)*N + n0 + c4]);
        tile[r][c4] = v.x; tile[r][c4+1] = v.y; tile[r][c4+2] = v.z; tile[r][c4+3] = v.w;
    }
    __syncthreads();
#pragma unroll
    for (int i = 0; i < 2; i++) {
        int idx = t + i*256;
        int r = idx >> 3, kc = (idx & 7) * 8;
        __half hs[8];
#pragma unroll
        for (int j = 0; j < 8; j++) hs[j] = __float2half(tile[kc + j][r]);
        *reinterpret_cast<uint4*>(&op[(size_t)(n0 + r)*K + k0 + kc]) = *reinterpret_cast<uint4*>(hs);
    }
}

// ================= tensor-core GEMM (fp16 x fp16 -> fp32) ==========================
// CTA 128x128, 4 warps of 64x64 warp tiles, BK=32, 4-stage ring, 2 CTAs/SM.
static constexpr int TILE_A   = 128 * 80;
static constexpr int TILE_BB  = 128 * 80;
static constexpr int STAGE_B  = TILE_A + TILE_BB;  // 20480 B
static constexpr int GEMM_DSMEM = 4 * STAGE_B;     // 81920 B

__device__ __forceinline__ void stage_load(uint32_t sdst,
        const __half* __restrict__ A, const __half* __restrict__ B,
        int m0, int n0, int K, int kk, int t) {
#pragma unroll
    for (int i = 0; i < 4; i++) {
        int id = t + i*128;
        int r  = id >> 2;
        int c8 = (id & 3) * 8;
        uint32_t soff = (uint32_t)(r * 80 + c8 * 2);
        cp_async16(sdst + soff,          A + (size_t)(m0 + r) * K + kk + c8);
        cp_async16(sdst + TILE_A + soff, B + (size_t)(n0 + r) * K + kk + c8);
    }
}

template <int MODE, bool GELU>
__global__ void __launch_bounds__(128, 2)
gemm_mma(const __half* __restrict__ A, const __half* __restrict__ B,
         const float* __restrict__ bias, const float* __restrict__ res,
         void* __restrict__ Cv, QKVPtrs P, int N, int K, float alpha)
{
    extern __shared__ char dsm[];
    const uint32_t sb = smem_u32(dsm);
    const int t = threadIdx.x, lane = t & 31, wid = t >> 5;
    const int wm = (wid & 1) * 64;
    const int wn = (wid >> 1) * 64;
    const int m0 = blockIdx.y * 128;
    const int n0 = blockIdx.x * 128;

    float acc[4][8][4];
#pragma unroll
    for (int i = 0; i < 4; i++)
#pragma unroll
        for (int j = 0; j < 8; j++)
#pragma unroll
            for (int d = 0; d < 4; d++) acc[i][j][d] = 0.f;

    const int S = K >> 5;

    const int arow = (lane & 7) + ((lane >> 3) & 1) * 8;
    const int akof = (lane >> 4) * 8;
    const int brow = (lane & 7) + ((lane >> 4) << 3);
    const int bkof = ((lane >> 3) & 1) * 8;

    stage_load(sb,             A, B, m0, n0, K, 0,  t); CP_COMMIT();
    stage_load(sb +   STAGE_B, A, B, m0, n0, K, 32, t); CP_COMMIT();
    stage_load(sb + 2*STAGE_B, A, B, m0, n0, K, 64, t); CP_COMMIT();

    for (int s = 0; s < S; s++) {
        CP_WAIT(2);
        __syncthreads();
        if (s + 3 < S)   // refill (s+3)&3 == (s-1)&3: consumed at s-1, safe after sync
            stage_load(sb + (uint32_t)((s + 3) & 3) * STAGE_B, A, B, m0, n0, K, (s + 3) << 5, t);
        CP_COMMIT();

        const uint32_t base = sb + (uint32_t)(s & 3) * STAGE_B;
#pragma unroll
        for (int ks = 0; ks < 2; ks++) {
            uint32_t bfr[4][4];
#pragma unroll
            for (int bi = 0; bi < 4; bi++)
                ldsm4(bfr[bi], base + TILE_A +
                      (uint32_t)((wn + bi*16 + brow) * 80 + (ks*16 + bkof) * 2));
#pragma unroll
            for (int mi = 0; mi < 4; mi++) {
                uint32_t af[4];
                ldsm4(af, base + (uint32_t)((wm + mi*16 + arow) * 80 + (ks*16 + akof) * 2));
#pragma unroll
                for (int nj = 0; nj < 8; nj++)
                    mma16816h(acc[mi][nj], af, &bfr[nj >> 1][(nj & 1) * 2]);
            }
        }
    }

    __half* hdst = nullptr;
    int nstride = N, ncol0 = n0;
    float alp = alpha;
    if (MODE == 2) {
        int nb = n0 >> 10;
        hdst = nb == 0 ? P.q : (nb == 1 ? P.k : P.v);
        alp = nb == 0 ? alpha : 1.0f;
        nstride = EMB;
        ncol0 = n0 & 1023;
    } else if (MODE == 1) {
        hdst = (__half*)Cv;
    }

#pragma unroll
    for (int mi = 0; mi < 4; mi++) {
#pragma unroll
        for (int half = 0; half < 2; half++) {
            int row = m0 + wm + mi*16 + (lane >> 2) + half * 8;
            const float* rrow = (MODE == 0 && res) ? res + (size_t)row * N : (const float*)nullptr;
#pragma unroll
            for (int nj = 0; nj < 8; nj++) {
                int coln = wn + nj*8 + (lane & 3) * 2;
                float vx = acc[mi][nj][half*2 + 0] * alp;
                float vy = acc[mi][nj][half*2 + 1] * alp;
                if (bias) { vx += bias[n0 + coln]; vy += bias[n0 + coln + 1]; }
                if (GELU) {
                    vx = 0.5f * vx * (1.f + erff(vx * 0.70710678118654752f));
                    vy = 0.5f * vy * (1.f + erff(vy * 0.70710678118654752f));
                }
                if (MODE == 0) {
                    int col = n0 + coln;
                    if (rrow) {
                        float2 r2 = *reinterpret_cast<const float2*>(rrow + col);
                        vx += r2.x; vy += r2.y;
                    }
                    *reinterpret_cast<float2*>((float*)Cv + (size_t)row * N + col) = make_float2(vx, vy);
                } else {
                    int col = ncol0 + coln;
                    *reinterpret_cast<__half2*>(hdst + (size_t)row * nstride + col) =
                        __halves2half2(__float2half(vx), __float2half(vy));
                }
            }
        }
    }
}

// ================= fused differential flash attention + sublayer RMS =================
// V loaded untransposed from vh; PV B-fragments via ldmatrix.trans. 2 syncs/chunk.
static constexpr int FQS = 72;      // K/Q/P row stride (halves)
static constexpr int VRS = 272;     // V row stride (bytes)
static constexpr int FA_STAGE = 36864;
static constexpr int FA_DSMEM = 36864 + 2*FA_STAGE;

__device__ __forceinline__ void fa_prefetch(uint32_t stg, const __half* __restrict__ kh,
                                            const __half* __restrict__ vh,
                                            int b, int h, int j0, int t) {
#pragma unroll
    for (int l = 0; l < 4; l++) {
        int x = t + l * 256;
        int map = x >> 9;
        int r = (x >> 3) & 63;
        int c8 = (x & 7) * 8;
        const __half* src = kh + (size_t)(b*SEQ + j0 + r) * EMB + (2*h + map)*64 + c8;
        cp_async16(stg + map*9216 + (uint32_t)(r*FQS + c8)*2, src);
    }
#pragma unroll
    for (int l = 0; l < 4; l++) {
        int x = t + l * 256;
        int r = x >> 4;
        int c8 = (x & 15) * 8;
        const __half* src = vh + (size_t)(b*SEQ + j0 + r) * EMB + h*DV + c8;
        cp_async16(stg + 18432 + (uint32_t)(r*VRS + c8*2), src);
    }
}

__global__ void __launch_bounds__(256, 2)
flash_kernel(const __half* __restrict__ qh, const __half* __restrict__ kh,
             const __half* __restrict__ vh, const float* __restrict__ subln,
             __half* __restrict__ ao)
{
    extern __shared__ char fsm[];
    __shared__ float red_l[2][2][64];
    __shared__ float red_sq[2][64];
    const uint32_t sb = smem_u32(fsm);

    const int t = threadIdx.x, lane = t & 31, wid = t >> 5;
    const int wm = (wid & 3) * 16;
    const int wn = wid >> 2;
    const int i0 = blockIdx.x * 64;
    const int h = blockIdx.y, b = blockIdx.z;
    const float lam = g_lam;

    const int arow = (lane & 7) + ((lane >> 3) & 1) * 8;
    const int akof = (lane >> 4) * 8;
    const int brow = (lane & 7) + ((lane >> 4) << 3);
    const int bkof = ((lane >> 3) & 1) * 8;
    const int tkrow = (lane & 7) + ((lane >> 3) & 1) * 8;
    const int tncol = ((lane >> 4) & 1) * 8;
    const int r0 = wm + (lane >> 2);

#pragma unroll
    for (int map = 0; map < 2; map++) {
        const __half* src = qh + (size_t)(b*SEQ + i0) * EMB + (2*h + map)*64;
        char* dst = fsm + map * 9216;
        for (int id = t; id < 512; id += 256) {
            int r = id >> 3, c8 = (id & 7) * 8;
            uint4 v = *reinterpret_cast<const uint4*>(src + (size_t)r * EMB + c8);
            *reinterpret_cast<uint4*>(dst + (r*FQS + c8)*2) = v;
        }
    }

    float Oacc[2][8][4];
#pragma unroll
    for (int m = 0; m < 2; m++)
#pragma unroll
        for (int f = 0; f < 8; f++)
#pragma unroll
            for (int d = 0; d < 4; d++) Oacc[m][f][d] = 0.f;
    float lst[2][2] = {{0.f, 0.f}, {0.f, 0.f}};

    fa_prefetch(sb + 36864, kh, vh, b, h, 0, t);
    CP_COMMIT();

    for (int c = 0; c < SEQ/64; c++) {
        const uint32_t cur = sb + 36864 + (uint32_t)(c & 1) * FA_STAGE;
        CP_WAIT(0);
        __syncthreads();
        if (c + 1 < SEQ/64) {
            fa_prefetch(sb + 36864 + (uint32_t)((c+1) & 1) * FA_STAGE, kh, vh, b, h, (c+1)*64, t);
            CP_COMMIT();
        }

#pragma unroll
        for (int map = 0; map < 2; map++) {
            float sacc[4][4];
#pragma unroll
            for (int f = 0; f < 4; f++)
#pragma unroll
                for (int d = 0; d < 4; d++) sacc[f][d] = 0.f;

            const uint32_t qbase = sb + (uint32_t)map * 9216;
            const uint32_t kbase = cur + (uint32_t)map * 9216;
#pragma unroll
            for (int ks = 0; ks < 4; ks++) {
                uint32_t af[4];
                ldsm4(af, qbase + (uint32_t)((wm + arow)*FQS + ks*16 + akof)*2);
                uint32_t bf[2][4];
#pragma unroll
                for (int bi = 0; bi < 2; bi++)
                    ldsm4(bf[bi], kbase + (uint32_t)((wn*32 + bi*16 + brow)*FQS + ks*16 + bkof)*2);
#pragma unroll
                for (int nj = 0; nj < 4; nj++)
                    mma16816h(sacc[nj], af, &bf[nj >> 1][(nj & 1)*2]);
            }

            float psum[2] = {0.f, 0.f};
#pragma unroll
            for (int nj = 0; nj < 4; nj++)
#pragma unroll
                for (int d = 0; d < 4; d++) {
                    float p = __expf(sacc[nj][d] - 4.0f);
                    sacc[nj][d] = p;
                    psum[d >> 1] += p;
                }
#pragma unroll
            for (int hf = 0; hf < 2; hf++) {
                psum[hf] += __shfl_xor_sync(0xffffffffu, psum[hf], 1);
                psum[hf] += __shfl_xor_sync(0xffffffffu, psum[hf], 2);
                lst[map][hf] += psum[hf];
            }

            char* pbase = fsm + 18432 + map * 9216;
#pragma unroll
            for (int nj = 0; nj < 4; nj++)
#pragma unroll
                for (int hf = 0; hf < 2; hf++) {
                    int row = r0 + hf * 8;
                    int col = wn*32 + nj*8 + (lane & 3)*2;
                    __half2 hp = __halves2half2(__float2half(sacc[nj][hf*2]),
                                                __float2half(sacc[nj][hf*2+1]));
                    *reinterpret_cast<__half2*>(pbase + (row*FQS + col)*2) = hp;
                }
        }
        __syncthreads();

        {
            const uint32_t p0 = sb + 18432;
            const uint32_t p1 = sb + 18432 + 9216;
            const uint32_t vbase = cur + 18432;
#pragma unroll
            for (int ks = 0; ks < 4; ks++) {
                uint32_t af0[4], af1[4];
                uint32_t poff = (uint32_t)((wm + arow)*FQS + ks*16 + akof)*2;
                ldsm4(af0, p0 + poff);
                ldsm4(af1, p1 + poff);
#pragma unroll
                for (int bi = 0; bi < 4; bi++) {
                    uint32_t bf[4];
                    ldsm4t(bf, vbase + (uint32_t)((ks*16 + tkrow)*VRS
                                                  + (wn*64 + bi*16 + tncol)*2));
                    mma16816h(Oacc[0][bi*2 + 0], af0, &bf[0]);
                    mma16816h(Oacc[0][bi*2 + 1], af0, &bf[2]);
                    mma16816h(Oacc[1][bi*2 + 0], af1, &bf[0]);
                    mma16816h(Oacc[1][bi*2 + 1], af1, &bf[2]);
                }
            }
        }
    }

    __syncthreads();
    if ((lane & 3) == 0) {
        red_l[0][wn][r0]     = lst[0][0];
        red_l[0][wn][r0 + 8] = lst[0][1];
        red_l[1][wn][r0]     = lst[1][0];
        red_l[1][wn][r0 + 8] = lst[1][1];
    }
    __syncthreads();

    float vals[2][8][2];
    float sq[2] = {0.f, 0.f};
#pragma unroll
    for (int hf = 0; hf < 2; hf++) {
        int rr = r0 + hf*8;
        float inv0 = 1.f / (red_l[0][0][rr] + red_l[0][1][rr]);
        float inv1 = 1.f / (red_l[1][0][rr] + red_l[1][1][rr]);
#pragma unroll
        for (int f = 0; f < 8; f++) {
            float vx = Oacc[0][f][hf*2+0]*inv0 - lam*Oacc[1][f][hf*2+0]*inv1;
            float vy = Oacc[0][f][hf*2+1]*inv0 - lam*Oacc[1][f][hf*2+1]*inv1;
            vals[hf][f][0] = vx; vals[hf][f][1] = vy;
            sq[hf] += vx*vx + vy*vy;
        }
    }
#pragma unroll
    for (int hf = 0; hf < 2; hf++) {
        sq[hf] += __shfl_xor_sync(0xffffffffu, sq[hf], 1);
        sq[hf] += __shfl_xor_sync(0xffffffffu, sq[hf], 2);
    }
    if ((lane & 3) == 0) {
        red_sq[wn][r0]     = sq[0];
        red_sq[wn][r0 + 8] = sq[1];
    }
    __syncthreads();

#pragma unroll
    for (int hf = 0; hf < 2; hf++) {
        int rr = r0 + hf*8;
        float tot = red_sq[0][rr] + red_sq[1][rr];
        float scale = rsqrtf(tot * (1.f/DV) + 1e-5f) * (1.f - LAM_INIT);
        int row = i0 + rr;
#pragma unroll
        for (int f = 0; f < 8; f++) {
            int cdv = wn*64 + f*8 + (lane & 3)*2;
            float2 w2 = *reinterpret_cast<const float2*>(subln + cdv);
            float vx = vals[hf][f][0] * scale * w2.x;
            float vy = vals[hf][f][1] * scale * w2.y;
            *reinterpret_cast<__half2*>(ao + (size_t)(b*SEQ + row)*EMB + h*DV + cdv) =
                __halves2half2(__float2half(vx), __float2half(vy));
        }
    }
}

// ---------------- lambda scalar ----------------
__global__ void lam_kernel(const float* __restrict__ lq1, const float* __restrict__ lk1,
                           const float* __restrict__ lq2, const float* __restrict__ lk2) {
    int t = threadIdx.x;
    float a = lq1[t]*lk1[t] + lq1[t+32]*lk1[t+32];
    float b = lq2[t]*lk2[t] + lq2[t+32]*lk2[t+32];
#pragma unroll
    for (int o = 16; o > 0; o >>= 1) {
        a += __shfl_down_sync(0xffffffffu, a, o);
        b += __shfl_down_sync(0xffffffffu, b, o);
    }
    if (t == 0) g_lam = expf(a) - expf(b) + LAM_INIT;
}

// ---------------- layernorm: fp32 in, fp16 out, vectorized ----------------
__global__ void ln_kernel(const float* __restrict__ x, const float* __restrict__ w,
                          const float* __restrict__ b, __half* __restrict__ out) {
    int row = blockIdx.x;
    const float* xr = x + (size_t)row*EMB;
    int t = threadIdx.x;
    float4 v = reinterpret_cast<const float4*>(xr)[t];     // 256 threads x 4
    float s  = v.x + v.y + v.z + v.w;
    float ss = v.x*v.x + v.y*v.y + v.z*v.z + v.w*v.w;
    __shared__ float shs[8], shss[8];
#pragma unroll
    for (int o = 16; o > 0; o >>= 1) {
        s  += __shfl_down_sync(0xffffffffu, s,  o);
        ss += __shfl_down_sync(0xffffffffu, ss, o);
    }
    int wid = t >> 5, lane = t & 31;
    if (lane == 0) { shs[wid] = s; shss[wid] = ss; }
    __syncthreads();
    if (t == 0) {
        float a = 0.f, c = 0.f;
#pragma unroll
        for (int i = 0; i < 8; i++) { a += shs[i]; c += shss[i]; }
        shs[0] = a; shss[0] = c;
    }
    __syncthreads();
    float mean = shs[0] * (1.f/EMB);
    float var  = shss[0] * (1.f/EMB) - mean*mean;
    float r = rsqrtf(var + 1e-5f);
    float4 w4 = reinterpret_cast<const float4*>(w)[t];
    float4 b4 = reinterpret_cast<const float4*>(b)[t];
    __half hs[4];
    hs[0] = __float2half((v.x - mean) * r * w4.x + b4.x);
    hs[1] = __float2half((v.y - mean) * r * w4.y + b4.y);
    hs[2] = __float2half((v.z - mean) * r * w4.z + b4.z);
    hs[3] = __float2half((v.w - mean) * r * w4.w + b4.w);
    reinterpret_cast<uint2*>(out + (size_t)row*EMB)[t] = *reinterpret_cast<uint2*>(hs);
}

// ---------------- launch ----------------
extern "C" void kernel_launch(void* const* d_in, const int* in_sizes, int n_in,
                              void* d_out, int out_size) {
    const float* x      = (const float*)d_in[0];
    const float* ln1_w  = (const float*)d_in[1];
    const float* ln1_b  = (const float*)d_in[2];
    const float* Wq     = (const float*)d_in[3];
    const float* Wk     = (const float*)d_in[4];
    const float* Wv     = (const float*)d_in[5];
    const float* Wo     = (const float*)d_in[6];
    const float* lq1    = (const float*)d_in[7];
    const float* lk1    = (const float*)d_in[8];
    const float* lq2    = (const float*)d_in[9];
    const float* lk2    = (const float*)d_in[10];
    const float* subln  = (const float*)d_in[11];
    const float* ln2_w  = (const float*)d_in[12];
    const float* ln2_b  = (const float*)d_in[13];
    const float* W1     = (const float*)d_in[14];
    const float* b1     = (const float*)d_in[15];
    const float* W2     = (const float*)d_in[16];
    const float* b2     = (const float*)d_in[17];
    float* out = (float*)d_out;

    __half *h, *qh, *kh, *vh, *ao, *ffi, *wbuf;
    float *x1;
    cudaGetSymbolAddress((void**)&h,   g_h);
    cudaGetSymbolAddress((void**)&qh,  g_qh);
    cudaGetSymbolAddress((void**)&kh,  g_kh);
    cudaGetSymbolAddress((void**)&vh,  g_vh);
    cudaGetSymbolAddress((void**)&ao,  g_ao);
    cudaGetSymbolAddress((void**)&ffi, g_t);
    cudaGetSymbolAddress((void**)&wbuf,g_w);
    cudaGetSymbolAddress((void**)&x1,  g_x1);

    cudaFuncSetAttribute(gemm_mma<0,false>, cudaFuncAttributeMaxDynamicSharedMemorySize, GEMM_DSMEM);
    cudaFuncSetAttribute(gemm_mma<1,true>,  cudaFuncAttributeMaxDynamicSharedMemorySize, GEMM_DSMEM);
    cudaFuncSetAttribute(gemm_mma<2,false>, cudaFuncAttributeMaxDynamicSharedMemorySize, GEMM_DSMEM);
    cudaFuncSetAttribute(flash_kernel,      cudaFuncAttributeMaxDynamicSharedMemorySize, FA_DSMEM);

    QKVPtrs qkv = {qh, kh, vh};
    QKVPtrs nop = {nullptr, nullptr, nullptr};

    const __half* wqkv = wbuf;
    const __half* wo   = wbuf + (size_t)3*1024*1024;
    const __half* w1h  = wbuf + (size_t)4*1024*1024;
    const __half* w2h  = wbuf + (size_t)8*1024*1024;

    lam_kernel<<<1, 32>>>(lq1, lk1, lq2, lk2);

    // all six weight conversions in one launch
    convert_w_all<<<3072, 256>>>(Wq, Wk, Wv, Wo, W1, W2, wbuf);

    ln_kernel<<<ROWS, 256>>>(x, ln1_w, ln1_b, h);

    // fused QKV GEMM (N=3072, q pre-scaled by 0.125)
    gemm_mma<2,false><<<dim3(3*EMB/128, ROWS/128), 128, GEMM_DSMEM>>>(
        h, wqkv, nullptr, nullptr, nullptr, qkv, 3*EMB, EMB, 0.125f);

    // fused differential flash attention + RMS -> ao
    flash_kernel<<<dim3(SEQ/64, NHEAD, BATCH), 256, FA_DSMEM>>>(qh, kh, vh, subln, ao);

    // x1 = x + ao @ Wo (fp32)
    gemm_mma<0,false><<<dim3(EMB/128, ROWS/128), 128, GEMM_DSMEM>>>(
        ao, wo, nullptr, x, x1, nop, EMB, EMB, 1.0f);

    ln_kernel<<<ROWS, 256>>>(x1, ln2_w, ln2_b, h);
    gemm_mma<1,true><<<dim3(FFD/128, ROWS/128), 128, GEMM_DSMEM>>>(
        h, w1h, b1, nullptr, ffi, nop, FFD, EMB, 1.0f);

    gemm_mma<0,false><<<dim3(EMB/128, ROWS/128), 128, GEMM_DSMEM>>>(
        ffi, w2h, b2, x1, out, nop, EMB, FFD, 1.0f);
}